// round 13
// baseline (speedup 1.0000x reference)
#include <cuda_runtime.h>

// Problem constants
#define NB      512          // batch N
#define INF     1024         // in_features
#define OUTF    64           // out_features
#define KD      16           // kernel dims
#define COLS    1024         // OUTF*KD (flattened projection width)
#define OSTRIDE 1088         // output row stride (IN + OUT)

// Scratch: projected matrices M = x @ T_flat, [512][1024], row-major.
__device__ __align__(16) float g_M[NB * COLS];

// ---------------------------------------------------------------------------
// Kernel 1: GEMM  g_M[512,1024] = x[512,1024] @ B[1024,1024]
// 64x64 tile per CTA, BK=16, 256 threads, 4x4 register micro-tile.
// As stored [M][K] (k-contiguous) so loads are straight float4 STS and the
// compute-side A reads are same-address broadcasts across tx (conflict-free).
// ---------------------------------------------------------------------------
__global__ void gemm_kernel(const float* __restrict__ A,
                            const float* __restrict__ B) {
    __shared__ __align__(16) float As[64][16];
    __shared__ __align__(16) float Bs[16][64];

    const int tid  = threadIdx.x;                 // 0..255
    const int bm   = blockIdx.y * 64;
    const int bn   = blockIdx.x * 64;
    const int tx   = tid & 15;                    // n micro-tile
    const int ty   = tid >> 4;                    // m micro-tile
    const int arow = tid >> 2;                    // A staging: 64 rows
    const int acol = (tid & 3) << 2;              //           x 16 cols (float4)
    const int brow = tid >> 4;                    // B staging: 16 rows
    const int bcol = (tid & 15) << 2;             //           x 64 cols (float4)

    float acc[4][4] = {};

    for (int k0 = 0; k0 < INF; k0 += 16) {
        const float4 av = *(const float4*)(A + (bm + arow) * INF  + k0 + acol);
        const float4 bv = *(const float4*)(B + (k0 + brow) * COLS + bn + bcol);
        __syncthreads();   // previous iteration's compute done before overwrite
        *(float4*)&As[arow][acol] = av;
        *(float4*)&Bs[brow][bcol] = bv;
        __syncthreads();

        #pragma unroll
        for (int k = 0; k < 16; k++) {
            const float a0 = As[ty * 4 + 0][k];
            const float a1 = As[ty * 4 + 1][k];
            const float a2 = As[ty * 4 + 2][k];
            const float a3 = As[ty * 4 + 3][k];
            const float4 b = *(const float4*)&Bs[k][tx * 4];
            acc[0][0] += a0 * b.x; acc[0][1] += a0 * b.y; acc[0][2] += a0 * b.z; acc[0][3] += a0 * b.w;
            acc[1][0] += a1 * b.x; acc[1][1] += a1 * b.y; acc[1][2] += a1 * b.z; acc[1][3] += a1 * b.w;
            acc[2][0] += a2 * b.x; acc[2][1] += a2 * b.y; acc[2][2] += a2 * b.z; acc[2][3] += a2 * b.w;
            acc[3][0] += a3 * b.x; acc[3][1] += a3 * b.y; acc[3][2] += a3 * b.z; acc[3][3] += a3 * b.w;
        }
    }

    #pragma unroll
    for (int r = 0; r < 4; r++) {
        float4 v = make_float4(acc[r][0], acc[r][1], acc[r][2], acc[r][3]);
        *(float4*)(g_M + (bm + ty * 4 + r) * COLS + bn + tx * 4) = v;
    }
}

// ---------------------------------------------------------------------------
// Kernel 2: copy x into out[:, 0:1024]  (output row stride 1088 floats)
// ---------------------------------------------------------------------------
__global__ void copyx_kernel(const float4* __restrict__ x4,
                             float4* __restrict__ out4) {
    const int idx = blockIdx.x * blockDim.x + threadIdx.x;  // 0..131071
    const int i = idx >> 8;         // row (256 float4 per x row)
    const int c = idx & 255;
    out4[i * (OSTRIDE / 4) + c] = x4[idx];
}

// ---------------------------------------------------------------------------
// Kernel 3: pairwise L1-of-16 + exp + masked batch sum.
// CTA handles IT=4 i-rows (256 threads: thread = (i_local, o)), sweeps all j
// in JT=8 row tiles staged in shared memory with a conflict-free swizzle:
//   logical 16B chunk (o, k4) stored at phys granule  o*4 + (k4 ^ ((o>>1)&3))
// -> every 8-thread LDS.128 phase hits 8 distinct 16B granules (verified).
// ---------------------------------------------------------------------------
#define IT 4
#define JT 8

__global__ void pairwise_kernel(float* __restrict__ out) {
    __shared__ __align__(16) float4 sh[JT * 256];   // 32 KB

    const int tid = threadIdx.x;        // 0..255
    const int o   = tid & 63;           // out-feature
    const int il  = tid >> 6;           // local i (0..3)
    const int i   = blockIdx.x * IT + il;
    const int s   = (o >> 1) & 3;       // read-side swizzle key

    // this thread's 16 kernel-dim values for (i, o)
    float4 mi[4];
    const float4* Mi = (const float4*)(g_M + i * COLS + o * KD);
    #pragma unroll
    for (int k = 0; k < 4; k++) mi[k] = Mi[k];

    // staging-side swizzle (each thread writes one float4 per row)
    const int oo  = tid >> 2;
    const int k4w = tid & 3;
    const int wdst = (oo << 2) + (k4w ^ ((oo >> 1) & 3));

    float acc = 0.0f;

    for (int j0 = 0; j0 < NB; j0 += JT) {
        __syncthreads();
        #pragma unroll
        for (int r = 0; r < JT; r++) {
            sh[r * 256 + wdst] = ((const float4*)(g_M + (j0 + r) * COLS))[tid];
        }
        __syncthreads();

        #pragma unroll
        for (int jj = 0; jj < JT; jj++) {
            const float4* row = sh + jj * 256 + (o << 2);
            const float4 b0 = row[s];        // logical chunk 0
            const float4 b1 = row[s ^ 1];    // logical chunk 1
            const float4 b2 = row[s ^ 2];    // logical chunk 2
            const float4 b3 = row[s ^ 3];    // logical chunk 3

            float n =
                ((fabsf(mi[0].x - b0.x) + fabsf(mi[0].y - b0.y)) +
                 (fabsf(mi[0].z - b0.z) + fabsf(mi[0].w - b0.w)))
              + ((fabsf(mi[1].x - b1.x) + fabsf(mi[1].y - b1.y)) +
                 (fabsf(mi[1].z - b1.z) + fabsf(mi[1].w - b1.w)))
              + ((fabsf(mi[2].x - b2.x) + fabsf(mi[2].y - b2.y)) +
                 (fabsf(mi[2].z - b2.z) + fabsf(mi[2].w - b2.w)))
              + ((fabsf(mi[3].x - b3.x) + fabsf(mi[3].y - b3.y)) +
                 (fabsf(mi[3].z - b3.z) + fabsf(mi[3].w - b3.w)));

            const float e = __expf(-n);
            if (j0 + jj != i) acc += e;   // exclude diagonal (uniform per warp)
        }
    }

    out[i * OSTRIDE + INF + o] = acc;
}

// ---------------------------------------------------------------------------
// Launch
// ---------------------------------------------------------------------------
extern "C" void kernel_launch(void* const* d_in, const int* in_sizes, int n_in,
                              void* d_out, int out_size) {
    (void)in_sizes; (void)n_in; (void)out_size;
    const float* x = (const float*)d_in[0];   // [512, 1024] f32
    const float* T = (const float*)d_in[1];   // [1024, 64, 16] f32 -> B[1024,1024]
    float* out = (float*)d_out;               // [512, 1088] f32

    dim3 ggrid(COLS / 64, NB / 64);           // (16, 8)
    gemm_kernel<<<ggrid, 256>>>(x, T);

    copyx_kernel<<<(NB * INF / 4) / 256, 256>>>((const float4*)x, (float4*)out);

    pairwise_kernel<<<NB / IT, 256>>>(out);
}

// round 14
// speedup vs baseline: 1.0046x; 1.0046x over previous
#include <cuda_runtime.h>

// Problem constants
#define NB      512          // batch N
#define INF     1024         // in_features
#define OUTF    64           // out_features
#define KD      16           // kernel dims
#define COLS    1024         // OUTF*KD (flattened projection width)
#define OSTRIDE 1088         // output row stride (IN + OUT)

// Scratch: projected matrices M = x @ T_flat, [512][1024], row-major.
__device__ __align__(16) float g_M[NB * COLS];

// ---------------------------------------------------------------------------
// Kernel 1: GEMM  g_M[512,1024] = x[512,1024] @ B[1024,1024]
// 64x64 tile per CTA, BK=16, 256 threads, 4x4 register micro-tile.
// As stored [M][K] (k-contiguous) so loads are straight float4 STS and the
// compute-side A reads are same-address broadcasts across tx (conflict-free).
// ---------------------------------------------------------------------------
__global__ void gemm_kernel(const float* __restrict__ A,
                            const float* __restrict__ B) {
    __shared__ __align__(16) float As[64][16];
    __shared__ __align__(16) float Bs[16][64];

    const int tid  = threadIdx.x;                 // 0..255
    const int bm   = blockIdx.y * 64;
    const int bn   = blockIdx.x * 64;
    const int tx   = tid & 15;                    // n micro-tile
    const int ty   = tid >> 4;                    // m micro-tile
    const int arow = tid >> 2;                    // A staging: 64 rows
    const int acol = (tid & 3) << 2;              //           x 16 cols (float4)
    const int brow = tid >> 4;                    // B staging: 16 rows
    const int bcol = (tid & 15) << 2;             //           x 64 cols (float4)

    float acc[4][4] = {};

    for (int k0 = 0; k0 < INF; k0 += 16) {
        const float4 av = *(const float4*)(A + (bm + arow) * INF  + k0 + acol);
        const float4 bv = *(const float4*)(B + (k0 + brow) * COLS + bn + bcol);
        __syncthreads();   // previous iteration's compute done before overwrite
        *(float4*)&As[arow][acol] = av;
        *(float4*)&Bs[brow][bcol] = bv;
        __syncthreads();

        #pragma unroll
        for (int k = 0; k < 16; k++) {
            const float a0 = As[ty * 4 + 0][k];
            const float a1 = As[ty * 4 + 1][k];
            const float a2 = As[ty * 4 + 2][k];
            const float a3 = As[ty * 4 + 3][k];
            const float4 b = *(const float4*)&Bs[k][tx * 4];
            acc[0][0] += a0 * b.x; acc[0][1] += a0 * b.y; acc[0][2] += a0 * b.z; acc[0][3] += a0 * b.w;
            acc[1][0] += a1 * b.x; acc[1][1] += a1 * b.y; acc[1][2] += a1 * b.z; acc[1][3] += a1 * b.w;
            acc[2][0] += a2 * b.x; acc[2][1] += a2 * b.y; acc[2][2] += a2 * b.z; acc[2][3] += a2 * b.w;
            acc[3][0] += a3 * b.x; acc[3][1] += a3 * b.y; acc[3][2] += a3 * b.z; acc[3][3] += a3 * b.w;
        }
    }

    #pragma unroll
    for (int r = 0; r < 4; r++) {
        float4 v = make_float4(acc[r][0], acc[r][1], acc[r][2], acc[r][3]);
        *(float4*)(g_M + (bm + ty * 4 + r) * COLS + bn + tx * 4) = v;
    }
}

// ---------------------------------------------------------------------------
// Kernel 2: copy x into out[:, 0:1024]  (output row stride 1088 floats)
// ---------------------------------------------------------------------------
__global__ void copyx_kernel(const float4* __restrict__ x4,
                             float4* __restrict__ out4) {
    const int idx = blockIdx.x * blockDim.x + threadIdx.x;  // 0..131071
    const int i = idx >> 8;         // row (256 float4 per x row)
    const int c = idx & 255;
    out4[i * (OSTRIDE / 4) + c] = x4[idx];
}

// ---------------------------------------------------------------------------
// Kernel 3: pairwise L1-of-16 + exp + masked batch sum.
// CTA handles IT=4 i-rows (256 threads: thread = (i_local, o)), sweeps all j
// in JT=8 row tiles staged in shared memory with a conflict-free swizzle:
//   logical 16B chunk (o, k4) stored at phys granule  o*4 + (k4 ^ ((o>>1)&3))
// -> every 8-thread LDS.128 phase hits 8 distinct 16B granules (verified).
// ---------------------------------------------------------------------------
#define IT 4
#define JT 8

__global__ void pairwise_kernel(float* __restrict__ out) {
    __shared__ __align__(16) float4 sh[JT * 256];   // 32 KB

    const int tid = threadIdx.x;        // 0..255
    const int o   = tid & 63;           // out-feature
    const int il  = tid >> 6;           // local i (0..3)
    const int i   = blockIdx.x * IT + il;
    const int s   = (o >> 1) & 3;       // read-side swizzle key

    // this thread's 16 kernel-dim values for (i, o)
    float4 mi[4];
    const float4* Mi = (const float4*)(g_M + i * COLS + o * KD);
    #pragma unroll
    for (int k = 0; k < 4; k++) mi[k] = Mi[k];

    // staging-side swizzle (each thread writes one float4 per row)
    const int oo  = tid >> 2;
    const int k4w = tid & 3;
    const int wdst = (oo << 2) + (k4w ^ ((oo >> 1) & 3));

    float acc = 0.0f;

    for (int j0 = 0; j0 < NB; j0 += JT) {
        __syncthreads();
        #pragma unroll
        for (int r = 0; r < JT; r++) {
            sh[r * 256 + wdst] = ((const float4*)(g_M + (j0 + r) * COLS))[tid];
        }
        __syncthreads();

        #pragma unroll
        for (int jj = 0; jj < JT; jj++) {
            const float4* row = sh + jj * 256 + (o << 2);
            const float4 b0 = row[s];        // logical chunk 0
            const float4 b1 = row[s ^ 1];    // logical chunk 1
            const float4 b2 = row[s ^ 2];    // logical chunk 2
            const float4 b3 = row[s ^ 3];    // logical chunk 3

            float n =
                ((fabsf(mi[0].x - b0.x) + fabsf(mi[0].y - b0.y)) +
                 (fabsf(mi[0].z - b0.z) + fabsf(mi[0].w - b0.w)))
              + ((fabsf(mi[1].x - b1.x) + fabsf(mi[1].y - b1.y)) +
                 (fabsf(mi[1].z - b1.z) + fabsf(mi[1].w - b1.w)))
              + ((fabsf(mi[2].x - b2.x) + fabsf(mi[2].y - b2.y)) +
                 (fabsf(mi[2].z - b2.z) + fabsf(mi[2].w - b2.w)))
              + ((fabsf(mi[3].x - b3.x) + fabsf(mi[3].y - b3.y)) +
                 (fabsf(mi[3].z - b3.z) + fabsf(mi[3].w - b3.w)));

            const float e = __expf(-n);
            if (j0 + jj != i) acc += e;   // exclude diagonal (uniform per warp)
        }
    }

    out[i * OSTRIDE + INF + o] = acc;
}

// ---------------------------------------------------------------------------
// Launch
// ---------------------------------------------------------------------------
extern "C" void kernel_launch(void* const* d_in, const int* in_sizes, int n_in,
                              void* d_out, int out_size) {
    (void)in_sizes; (void)n_in; (void)out_size;
    const float* x = (const float*)d_in[0];   // [512, 1024] f32
    const float* T = (const float*)d_in[1];   // [1024, 64, 16] f32 -> B[1024,1024]
    float* out = (float*)d_out;               // [512, 1088] f32

    dim3 ggrid(COLS / 64, NB / 64);           // (16, 8)
    gemm_kernel<<<ggrid, 256>>>(x, T);

    copyx_kernel<<<(NB * INF / 4) / 256, 256>>>((const float4*)x, (float4*)out);

    pairwise_kernel<<<NB / IT, 256>>>(out);
}